// round 1
// baseline (speedup 1.0000x reference)
#include <cuda_runtime.h>
#include <cstdint>

#define NB 16
#define NN 128
#define NH 256

// Scratch (no runtime allocation allowed)
__device__ float g_xwb[NB * NN * NH];      // inputs@W_atom + 0.5*b_bin  (2 MB)
__device__ float g_wbin[NH * NH];          // W_bin pre-rounded to tf32  (256 KB)
__device__ float g_partial[NB * NN * 2];   // per-(b,i) score partials, one per khalf

// ---------------- helpers ----------------
__device__ __forceinline__ uint32_t f2tf32(float x) {
    uint32_t r;
    asm("cvt.rna.tf32.f32 %0, %1;" : "=r"(r) : "f"(x));
    return r;
}
__device__ __forceinline__ void cp16(uint32_t dst, const void* src) {
    asm volatile("cp.async.cg.shared.global [%0], [%1], 16;" :: "r"(dst), "l"(src));
}
__device__ __forceinline__ void cp_commit() { asm volatile("cp.async.commit_group;"); }
template <int N> __device__ __forceinline__ void cp_wait() {
    asm volatile("cp.async.wait_group %0;" :: "n"(N));
}
__device__ __forceinline__ void mma_tf32(float* c, const uint32_t* a, uint32_t b0, uint32_t b1) {
    asm volatile(
        "mma.sync.aligned.m16n8k8.row.col.f32.tf32.tf32.f32 "
        "{%0,%1,%2,%3}, {%4,%5,%6,%7}, {%8,%9}, {%0,%1,%2,%3};"
        : "+f"(c[0]), "+f"(c[1]), "+f"(c[2]), "+f"(c[3])
        : "r"(a[0]), "r"(a[1]), "r"(a[2]), "r"(a[3]), "r"(b0), "r"(b1));
}

// ---------------- kernel 1: xwb = inputs@W_atom + 0.5*b_bin; W_bin -> tf32 ----------------
__global__ __launch_bounds__(256) void k_prep(
    const float* __restrict__ inp, const float* __restrict__ Wa,
    const float* __restrict__ Wb, const float* __restrict__ bb)
{
    __shared__ float s_in[16 * NH];
    const int tid = threadIdx.x;
    const int base = blockIdx.x * 16;  // 16 rows of the 2048 (b,n) rows

    for (int c = tid; c < 1024; c += 256)
        ((float4*)s_in)[c] = ((const float4*)(inp + (size_t)base * NH))[c];
    __syncthreads();

    float acc[16];
#pragma unroll
    for (int r = 0; r < 16; r++) acc[r] = 0.f;

    const int k = tid;  // output column
    for (int h = 0; h < NH; h++) {
        float w = Wa[h * NH + k];
#pragma unroll
        for (int r = 0; r < 16; r++) acc[r] = fmaf(s_in[r * NH + h], w, acc[r]);
    }
    const float bk = 0.5f * bb[k];
#pragma unroll
    for (int r = 0; r < 16; r++) g_xwb[(size_t)(base + r) * NH + k] = acc[r] + bk;

    // W_bin -> tf32-rounded bits (65536 elems / 128 blocks = 512 per block)
    const int off = blockIdx.x * 512;
    for (int t = tid; t < 512; t += 256)
        g_wbin[off + t] = __uint_as_float(f2tf32(Wb[off + t]));
}

// ---------------- kernel 2: fused GEMM + relu-dot + atom_pair ----------------
// grid (khalf, i, b) = (2, 128, 16). CTA tile: M=128 (j) x N=128 (k-half), K=256.
// smem mainloop: A[2][128][36] (9216 f) + B[2][32][136] (8704 f) = 17920 floats = 71680 B
// smem epilogue (reused): xwj[128][132] (16896) + xwi[128] + wsc[128] = 17152 floats
__global__ __launch_bounds__(256, 2) void k_main(
    const float* __restrict__ bin, const float* __restrict__ inp,
    const float* __restrict__ wsc, float* __restrict__ out_pair)
{
    extern __shared__ float sm[];
    __shared__ float s_red[8];

    const int khalf = blockIdx.x;
    const int i = blockIdx.y;
    const int b = blockIdx.z;
    const int tid = threadIdx.x;
    const int warp = tid >> 5, lane = tid & 31;
    const int wm = warp & 3, wn = warp >> 2;   // 4 x 2 warp grid
    const int g = lane >> 2, tig = lane & 3;
    const int nbase = khalf * 128;

    float* sA = sm;          // 2 * 128 * 36
    float* sB = sm + 9216;   // 2 * 32 * 136
    const float* binrow = bin + (size_t)(b * NN + i) * NN * NH;

    float acc[2][8][4];
#pragma unroll
    for (int a = 0; a < 2; a++)
#pragma unroll
        for (int x = 0; x < 8; x++)
#pragma unroll
            for (int y = 0; y < 4; y++) acc[a][x][y] = 0.f;

    auto load_tiles = [&](int it) {
        const int buf = it & 1;
        const int kb = it << 5;  // K chunk base (32 per iter)
        float* dA = sA + buf * 4608;
#pragma unroll
        for (int c = 0; c < 4; c++) {
            int cc = tid + c * 256;
            int j = cc >> 3, coff = (cc & 7) << 2;
            cp16((uint32_t)__cvta_generic_to_shared(dA + j * 36 + coff),
                 binrow + j * NH + kb + coff);
        }
        float* dB = sB + buf * 4352;
#pragma unroll
        for (int c = 0; c < 4; c++) {
            int cc = tid + c * 256;
            int k = cc >> 5, coff = (cc & 31) << 2;
            cp16((uint32_t)__cvta_generic_to_shared(dB + k * 136 + coff),
                 g_wbin + (kb + k) * NH + nbase + coff);
        }
    };

    load_tiles(0);
    cp_commit();

    // atom_pair streaming store — overlap with async loads / MMA warmup.
    if (khalf == 0) {
        float* po = out_pair + (size_t)(b * NN + i) * NN * NH;
        const float* xi = inp + (size_t)(b * NN + i) * NH;
        const float* xb = inp + (size_t)b * NN * NH;
#pragma unroll 4
        for (int c = tid; c < 8192; c += 256) {
            int j = c >> 6, h4 = (c & 63) << 2;
            float4 vi = *(const float4*)(xi + h4);
            float4 vj = *(const float4*)(xb + j * NH + h4);
            float4 o = make_float4(vi.x + vj.x, vi.y + vj.y, vi.z + vj.z, vi.w + vj.w);
            *(float4*)(po + j * NH + h4) = o;
        }
    }

#pragma unroll 1
    for (int it = 0; it < 8; it++) {
        if (it < 7) { load_tiles(it + 1); cp_commit(); cp_wait<1>(); }
        else        { cp_wait<0>(); }
        __syncthreads();

        const float* A  = sA + (it & 1) * 4608;
        const float* Bt = sB + (it & 1) * 4352;
#pragma unroll
        for (int kk = 0; kk < 32; kk += 8) {
            uint32_t afrag[2][4];
#pragma unroll
            for (int mt = 0; mt < 2; mt++) {
                int r = wm * 32 + mt * 16 + g;
                afrag[mt][0] = f2tf32(A[r * 36 + kk + tig]);
                afrag[mt][1] = f2tf32(A[(r + 8) * 36 + kk + tig]);
                afrag[mt][2] = f2tf32(A[r * 36 + kk + tig + 4]);
                afrag[mt][3] = f2tf32(A[(r + 8) * 36 + kk + tig + 4]);
            }
#pragma unroll
            for (int nt = 0; nt < 8; nt++) {
                int n = wn * 64 + nt * 8 + g;
                uint32_t b0 = __float_as_uint(Bt[(kk + tig) * 136 + n]);
                uint32_t b1 = __float_as_uint(Bt[(kk + tig + 4) * 136 + n]);
                mma_tf32(acc[0][nt], afrag[0], b0, b1);
                mma_tf32(acc[1][nt], afrag[1], b0, b1);
            }
        }
        __syncthreads();
    }

    // ---- epilogue: stage xwb rows for this (b, khalf) into reused smem ----
    float* sXJ = sm;            // [128][132]
    float* sXI = sm + 16896;    // [128]
    float* sW  = sm + 17024;    // [128]
    const float* xw_b = g_xwb + (size_t)(b * NN) * NH + nbase;
#pragma unroll 4
    for (int c = tid; c < 4096; c += 256) {
        int j = c >> 5, coff = (c & 31) << 2;
        *(float4*)(sXJ + j * 132 + coff) = *(const float4*)(xw_b + j * NH + coff);
    }
    if (tid < 32) {
        *(float4*)(sXI + tid * 4) =
            *(const float4*)(g_xwb + (size_t)(b * NN + i) * NH + nbase + tid * 4);
        *(float4*)(sW + tid * 4) = *(const float4*)(wsc + nbase + tid * 4);
    }
    __syncthreads();

    float local = 0.f;
#pragma unroll
    for (int mt = 0; mt < 2; mt++) {
        int j0 = wm * 32 + mt * 16 + g;
#pragma unroll
        for (int nt = 0; nt < 8; nt++) {
            int k = wn * 64 + nt * 8 + tig * 2;
            float xi0 = sXI[k], xi1 = sXI[k + 1];
            float w0 = sW[k],  w1 = sW[k + 1];
            float xj00 = sXJ[j0 * 132 + k],       xj01 = sXJ[j0 * 132 + k + 1];
            float xj10 = sXJ[(j0 + 8) * 132 + k], xj11 = sXJ[(j0 + 8) * 132 + k + 1];
            local += fmaxf(acc[mt][nt][0] + xi0 + xj00, 0.f) * w0;
            local += fmaxf(acc[mt][nt][1] + xi1 + xj01, 0.f) * w1;
            local += fmaxf(acc[mt][nt][2] + xi0 + xj10, 0.f) * w0;
            local += fmaxf(acc[mt][nt][3] + xi1 + xj11, 0.f) * w1;
        }
    }
#pragma unroll
    for (int o = 16; o; o >>= 1) local += __shfl_xor_sync(0xffffffffu, local, o);
    if (lane == 0) s_red[warp] = local;
    __syncthreads();
    if (tid == 0) {
        float s = 0.f;
#pragma unroll
        for (int w = 0; w < 8; w++) s += s_red[w];
        g_partial[(b * NN + i) * 2 + khalf] = s;  // deterministic, no atomics
    }
}

// ---------------- kernel 3: att_context = scalar * inputs ----------------
__global__ __launch_bounds__(256) void k_final(
    const float* __restrict__ inp, const float* __restrict__ bsc,
    float* __restrict__ out_ctx)
{
    const int row = blockIdx.x;  // 0..2047 = (b,i)
    const float s = g_partial[row * 2] + g_partial[row * 2 + 1] + 128.f * bsc[0];
    out_ctx[(size_t)row * NH + threadIdx.x] = s * inp[(size_t)row * NH + threadIdx.x];
}

// ---------------- launch ----------------
extern "C" void kernel_launch(void* const* d_in, const int* in_sizes, int n_in,
                              void* d_out, int out_size)
{
    const float* inputs  = (const float*)d_in[0];
    const float* bin     = (const float*)d_in[1];
    const float* W_atom  = (const float*)d_in[2];
    const float* W_bin   = (const float*)d_in[3];
    const float* b_bin   = (const float*)d_in[4];
    const float* w_score = (const float*)d_in[5];
    const float* b_score = (const float*)d_in[6];

    float* out_ctx  = (float*)d_out;                 // [B,N,H] first
    float* out_pair = out_ctx + NB * NN * NH;        // then [B,N,N,H]

    cudaFuncSetAttribute(k_main, cudaFuncAttributeMaxDynamicSharedMemorySize, 71680);

    k_prep<<<128, 256>>>(inputs, W_atom, W_bin, b_bin);
    k_main<<<dim3(2, NN, NB), 256, 71680>>>(bin, inputs, w_score, out_pair);
    k_final<<<NB * NN, 256>>>(inputs, b_score, out_ctx);
}

// round 4
// speedup vs baseline: 1.4390x; 1.4390x over previous
#include <cuda_runtime.h>
#include <cuda_fp16.h>
#include <cstdint>

#define NB 16
#define NN 128
#define NH 256

// ---------------- scratch (static, no runtime allocation) ----------------
__device__ float g_xwb[NB * NN * NH];                 // inputs@W_atom + 0.5*b_bin (fp32, 2 MB)
__device__ __align__(16) __half g_wbinT_h[NH * NH];   // W_bin transposed [n][h], fp16 (128 KB)

// ---------------- helpers ----------------
__device__ __forceinline__ uint32_t s2u(const void* p) {
    return (uint32_t)__cvta_generic_to_shared(p);
}
__device__ __forceinline__ void cp16(uint32_t d, const void* s) {
    asm volatile("cp.async.cg.shared.global [%0], [%1], 16;" :: "r"(d), "l"(s));
}
__device__ __forceinline__ void cp_commit() { asm volatile("cp.async.commit_group;"); }
template <int N> __device__ __forceinline__ void cp_wait() {
    asm volatile("cp.async.wait_group %0;" :: "n"(N));
}
__device__ __forceinline__ uint32_t packh2(float x, float y) {
    __half2 h = __floats2half2_rn(x, y);
    return *(uint32_t*)&h;
}
__device__ __forceinline__ void mma_f16(float* c, const uint32_t* a, uint32_t b0, uint32_t b1) {
    asm volatile(
        "mma.sync.aligned.m16n8k16.row.col.f32.f16.f16.f32 "
        "{%0,%1,%2,%3}, {%4,%5,%6,%7}, {%8,%9}, {%0,%1,%2,%3};"
        : "+f"(c[0]), "+f"(c[1]), "+f"(c[2]), "+f"(c[3])
        : "r"(a[0]), "r"(a[1]), "r"(a[2]), "r"(a[3]), "r"(b0), "r"(b1));
}

// ---------------- kernel 1: xwb = inputs@W_atom + 0.5*b_bin ; W_bin^T -> fp16 ----------------
__global__ __launch_bounds__(256) void k_prep(
    const float* __restrict__ inp, const float* __restrict__ Wa,
    const float* __restrict__ Wb, const float* __restrict__ bb)
{
    __shared__ float sh[2112];
    const int tid = threadIdx.x;
    const int bid = blockIdx.x;

    if (bid < 256) {
        // xwb rows [bid*8, bid*8+8): 8 rows x 256 cols, MLP>=4 via float4 W loads
        const int base = bid * 8;
        for (int c = tid; c < 512; c += 256)
            ((float4*)sh)[c] = ((const float4*)(inp + (size_t)base * NH))[c];
        __syncthreads();

        const int quad = tid & 63;
        const int c0 = quad * 4;
        const int r0 = (tid >> 6) * 2;
        float acc0[4] = {0, 0, 0, 0}, acc1[4] = {0, 0, 0, 0};
        const float* s0 = sh + r0 * NH;
        const float* s1 = sh + (r0 + 1) * NH;
#pragma unroll 4
        for (int h = 0; h < NH; h++) {
            float4 w = *(const float4*)(Wa + (size_t)h * NH + c0);
            float a0 = s0[h], a1 = s1[h];
            acc0[0] = fmaf(a0, w.x, acc0[0]); acc0[1] = fmaf(a0, w.y, acc0[1]);
            acc0[2] = fmaf(a0, w.z, acc0[2]); acc0[3] = fmaf(a0, w.w, acc0[3]);
            acc1[0] = fmaf(a1, w.x, acc1[0]); acc1[1] = fmaf(a1, w.y, acc1[1]);
            acc1[2] = fmaf(a1, w.z, acc1[2]); acc1[3] = fmaf(a1, w.w, acc1[3]);
        }
        float4 bv = *(const float4*)(bb + c0);
        *(float4*)(g_xwb + (size_t)(base + r0) * NH + c0) =
            make_float4(acc0[0] + 0.5f * bv.x, acc0[1] + 0.5f * bv.y,
                        acc0[2] + 0.5f * bv.z, acc0[3] + 0.5f * bv.w);
        *(float4*)(g_xwb + (size_t)(base + r0 + 1) * NH + c0) =
            make_float4(acc1[0] + 0.5f * bv.x, acc1[1] + 0.5f * bv.y,
                        acc1[2] + 0.5f * bv.z, acc1[3] + 0.5f * bv.w);
    } else {
        // transpose 32x32 tile of W_bin -> g_wbinT_h[n][h] (fp16)
        const int t = bid - 256;
        const int nb = (t >> 3) * 32, hb = (t & 7) * 32;
        const int ty = tid >> 5, tx = tid & 31;
#pragma unroll
        for (int r = 0; r < 4; r++) {
            int hl = ty + r * 8;
            sh[hl * 33 + tx] = Wb[(size_t)(hb + hl) * NH + nb + tx];
        }
        __syncthreads();
#pragma unroll
        for (int r = 0; r < 4; r++) {
            int nl = ty + r * 8;
            g_wbinT_h[(size_t)(nb + nl) * NH + hb + tx] = __float2half_rn(sh[tx * 33 + nl]);
        }
    }
}

// ---------------- kernel 2: fp16 MMA GEMM + fused epilogue + atom_pair ----------------
// One CTA per (b,i): D[j,n] = sum_h bin[b,i,j,h]*W_bin[h,n], M=128, N=256, K=256.
// 512 threads = 16 warps in 4(m) x 4(n); warp tile 32x64; K chunked by 32, double-buffered.
// SMEM: A f32 [2][128][36] (36864 B), B fp16 [2][256][40] (40960 B), sW 1KB, sXI 1KB.
#define OFF_B   36864
#define OFF_W   77824
#define OFF_XI  78848
#define SMEM_MAIN 79872
#define A_BUF   18432
#define B_BUF   20480

__global__ __launch_bounds__(512) void k_main(
    const float* __restrict__ bin, const float* __restrict__ inp,
    const float* __restrict__ wsc, const float* __restrict__ bsc,
    float* __restrict__ out_pair, float* __restrict__ out_ctx)
{
    extern __shared__ char smc[];
    __shared__ float s_red[17];

    const int tid = threadIdx.x;
    const int warp = tid >> 5, lane = tid & 31;
    const int wm = warp & 3, wn = warp >> 2;     // 4 x 4 warp grid
    const int g = lane >> 2, tig = lane & 3;
    const int i = blockIdx.x & 127;
    const int b = blockIdx.x >> 7;

    const uint32_t sbA = s2u(smc);
    const uint32_t sbB = sbA + OFF_B;
    const float* binrow = bin + (size_t)(b * NN + i) * NN * NH;

    float acc[2][8][4];
#pragma unroll
    for (int m = 0; m < 2; m++)
#pragma unroll
        for (int x = 0; x < 8; x++)
#pragma unroll
            for (int y = 0; y < 4; y++) acc[m][x][y] = 0.f;

    auto load_chunk = [&](int c) {
        const int kb = c << 5;
        const int buf = c & 1;
#pragma unroll
        for (int u = 0; u < 2; u++) {                 // A: 128x32 f32, row stride 144B
            int idx = tid + u * 512;
            int j = idx >> 3, w = idx & 7;
            cp16(sbA + buf * A_BUF + j * 144 + w * 16,
                 binrow + (size_t)j * NH + kb + w * 4);
        }
#pragma unroll
        for (int u = 0; u < 2; u++) {                 // B: 256x32 fp16, row stride 80B
            int idx = tid + u * 512;
            int n = idx >> 2, w = idx & 3;
            cp16(sbB + buf * B_BUF + n * 80 + w * 16,
                 g_wbinT_h + (size_t)n * NH + kb + w * 8);
        }
        cp_commit();
    };

    load_chunk(0);

    // stage per-column vectors
    if (tid < 64) {
        *(float4*)(smc + OFF_W + tid * 16) = *(const float4*)(wsc + tid * 4);
    } else if (tid < 128) {
        int t = tid - 64;
        *(float4*)(smc + OFF_XI + t * 16) =
            *(const float4*)(g_xwb + (size_t)(b * NN + i) * NH + t * 4);
    }

    // atom_pair streaming store (writes drain while MMA runs)
    {
        float* po = out_pair + (size_t)(b * NN + i) * NN * NH;
        const float* xi = inp + (size_t)(b * NN + i) * NH;
        const float* xb = inp + (size_t)b * NN * NH;
#pragma unroll 4
        for (int c = tid; c < 8192; c += 512) {
            int j = c >> 6, h4 = (c & 63) << 2;
            float4 vi = *(const float4*)(xi + h4);
            float4 vj = *(const float4*)(xb + (size_t)j * NH + h4);
            *(float4*)(po + (size_t)j * NH + h4) =
                make_float4(vi.x + vj.x, vi.y + vj.y, vi.z + vj.z, vi.w + vj.w);
        }
    }

#pragma unroll 1
    for (int it = 0; it < 8; it++) {
        if (it < 7) { load_chunk(it + 1); cp_wait<1>(); }
        else        { cp_wait<0>(); }
        __syncthreads();

        const float* As = (const float*)(smc + (it & 1) * A_BUF);
        const char*  Bs = smc + OFF_B + (it & 1) * B_BUF;
#pragma unroll
        for (int ks = 0; ks < 32; ks += 16) {
            uint32_t a[2][4];
#pragma unroll
            for (int mt = 0; mt < 2; mt++) {
                int r = wm * 32 + mt * 16 + g;
                float2 p0 = *(const float2*)(As + r * 36 + ks + tig * 2);
                float2 p1 = *(const float2*)(As + (r + 8) * 36 + ks + tig * 2);
                float2 p2 = *(const float2*)(As + r * 36 + ks + tig * 2 + 8);
                float2 p3 = *(const float2*)(As + (r + 8) * 36 + ks + tig * 2 + 8);
                a[mt][0] = packh2(p0.x, p0.y);
                a[mt][1] = packh2(p1.x, p1.y);
                a[mt][2] = packh2(p2.x, p2.y);
                a[mt][3] = packh2(p3.x, p3.y);
            }
#pragma unroll
            for (int nt = 0; nt < 8; nt++) {
                int n = wn * 64 + nt * 8 + g;
                uint32_t b0 = *(const uint32_t*)(Bs + n * 80 + (ks + tig * 2) * 2);
                uint32_t b1 = *(const uint32_t*)(Bs + n * 80 + (ks + tig * 2 + 8) * 2);
                mma_f16(acc[0][nt], a[0], b0, b1);
                mma_f16(acc[1][nt], a[1], b0, b1);
            }
        }
        __syncthreads();
    }

    // epilogue: relu(D + xwi + xwj) . w_score, reduce over (j,n)
    const float* sW  = (const float*)(smc + OFF_W);
    const float* sXI = (const float*)(smc + OFF_XI);
    const float* xwb_b = g_xwb + (size_t)b * NN * NH;

    float partial = 0.f;
#pragma unroll
    for (int mt = 0; mt < 2; mt++) {
        int j0 = wm * 32 + mt * 16 + g;
        const float* xj0 = xwb_b + (size_t)j0 * NH;
        const float* xj1 = xwb_b + (size_t)(j0 + 8) * NH;
#pragma unroll
        for (int nt = 0; nt < 8; nt++) {
            int k = wn * 64 + nt * 8 + tig * 2;
            float2 w  = *(const float2*)(sW + k);
            float2 xi = *(const float2*)(sXI + k);
            float2 xa = *(const float2*)(xj0 + k);
            float2 xb2 = *(const float2*)(xj1 + k);
            partial = fmaf(fmaxf(acc[mt][nt][0] + xi.x + xa.x, 0.f), w.x, partial);
            partial = fmaf(fmaxf(acc[mt][nt][1] + xi.y + xa.y, 0.f), w.y, partial);
            partial = fmaf(fmaxf(acc[mt][nt][2] + xi.x + xb2.x, 0.f), w.x, partial);
            partial = fmaf(fmaxf(acc[mt][nt][3] + xi.y + xb2.y, 0.f), w.y, partial);
        }
    }
#pragma unroll
    for (int o = 16; o; o >>= 1) partial += __shfl_xor_sync(0xffffffffu, partial, o);
    if (lane == 0) s_red[warp] = partial;
    __syncthreads();
    if (tid == 0) {
        float s = 0.f;
#pragma unroll
        for (int w = 0; w < 16; w++) s += s_red[w];
        s_red[16] = s + 128.f * bsc[0];
    }
    __syncthreads();

    if (tid < NH) {
        const float s = s_red[16];
        out_ctx[(size_t)(b * NN + i) * NH + tid] =
            s * inp[(size_t)(b * NN + i) * NH + tid];
    }
}

// ---------------- launch ----------------
extern "C" void kernel_launch(void* const* d_in, const int* in_sizes, int n_in,
                              void* d_out, int out_size)
{
    const float* inputs  = (const float*)d_in[0];
    const float* bin     = (const float*)d_in[1];
    const float* W_atom  = (const float*)d_in[2];
    const float* W_bin   = (const float*)d_in[3];
    const float* b_bin   = (const float*)d_in[4];
    const float* w_score = (const float*)d_in[5];
    const float* b_score = (const float*)d_in[6];

    float* out_ctx  = (float*)d_out;
    float* out_pair = out_ctx + NB * NN * NH;

    cudaFuncSetAttribute(k_main, cudaFuncAttributeMaxDynamicSharedMemorySize, SMEM_MAIN);

    k_prep<<<320, 256>>>(inputs, W_atom, W_bin, b_bin);
    k_main<<<NB * NN, 512, SMEM_MAIN>>>(bin, inputs, w_score, b_score,
                                        out_pair, out_ctx);
}